// round 14
// baseline (speedup 1.0000x reference)
#include <cuda_runtime.h>
#include <math_constants.h>

#define B_      4
#define C_      256
#define H_      64
#define W_      64
#define NROI    128
#define THREADS 256

// Block = (b, 2-channel group, roi-parity). Stage 2 planes float2-interleaved
// (32 KB -> 6 blocks/SM); thread-per-bin tasks read 2 channels per LDS.64.
// Bin bounds: exact integer math, bit-identical to reference f32 bounds
// (rel_err == 0, rounds 4-13). Deterministic ballot compaction (R10).
__global__ __launch_bounds__(THREADS) void roi_pool_c2hi(
    const float* __restrict__ feat,
    const int*   __restrict__ rois,
    float*       __restrict__ out)
{
    __shared__ __align__(16) float2 plane2[H_ * W_];        // 32 KB
    __shared__ int s_idx[NROI], s_x1[NROI], s_y1[NROI];
    __shared__ unsigned char s_hb[NROI][8], s_wb[NROI][8];
    __shared__ int s_wcnt[4];

    const int tid  = threadIdx.x;
    const int lane = tid & 31;
    const int wid  = tid >> 5;
    const int blk  = blockIdx.x;            // ((b*128 + grp) << 1) | half
    const int half = blk & 1;
    const int bcp  = blk >> 1;
    const int b    = bcp >> 7;
    const int c0   = (bcp & 127) << 1;      // channels c0, c0+1

    // ---- phase 0: deterministic compaction (order = original roi index) ----
    bool match = false;
    if (tid < NROI)
        match = (__ldg(rois + tid * 5) == b);
    const unsigned mball = __ballot_sync(0xffffffffu, match);
    if (lane == 0 && wid < 4) s_wcnt[wid] = __popc(mball);
    __syncthreads();
    const int cnt = s_wcnt[0] + s_wcnt[1] + s_wcnt[2] + s_wcnt[3];

    if (match) {
        int p = __popc(mball & ((1u << lane) - 1u));
        for (int w = 0; w < wid; ++w) p += s_wcnt[w];
        const int x1 = __ldg(rois + tid * 5 + 1);
        const int y1 = __ldg(rois + tid * 5 + 2);
        const int x2 = __ldg(rois + tid * 5 + 3);
        const int y2 = __ldg(rois + tid * 5 + 4);
        const int rh = y2 - y1 + 1;          // 5..48
        const int rw = x2 - x1 + 1;          // 5..48
        s_idx[p] = tid;
        s_x1[p]  = x1;
        s_y1[p]  = y1;
        #pragma unroll
        for (int i = 0; i < 8; ++i) {
            s_hb[p][i] = (unsigned char)((i * rh) / 7);
            s_wb[p][i] = (unsigned char)((i * rw) / 7);
        }
    }

    // ---- phase 1: stage 2 planes float2-interleaved, conflict-free ----
    // out4[h] covers pixels 2h, 2h+1: {f0[2h], f1[2h], f0[2h+1], f1[2h+1]}
    {
        const float2* f0 = (const float2*)(feat + ((size_t)b * C_ + c0) * (H_ * W_));
        const float2* f1 = f0 + (H_ * W_ / 2);
        float4* out4 = (float4*)plane2;
        #pragma unroll
        for (int kk = 0; kk < 8; ++kk) {
            const int h = kk * THREADS + tid;          // 0..2047
            const float2 a = __ldg(f0 + h);
            const float2 c = __ldg(f1 + h);
            out4[h] = make_float4(a.x, c.x, a.y, c.y);
        }
    }
    __syncthreads();

    // ---- phase 2: thread-per-bin tasks over my roi half, 2 channels each ----
    const int nmine = (cnt > half) ? ((cnt - half + 1) >> 1) : 0;
    const int total = nmine * 49;
    for (int u = tid; u < total; u += THREADS) {
        const int km  = u / 49;
        const int bin = u - km * 49;
        const int k   = half + (km << 1);
        const int i   = (bin * 9363) >> 16;            // bin / 7 for bin < 49
        const int j   = bin - i * 7;

        const int hs = s_hb[k][i], he = s_hb[k][i + 1];
        const int ws = s_wb[k][j], we = s_wb[k][j + 1];
        const int nx = we - ws;
        const bool valid = (he > hs) && (nx > 0);

        int idx = (s_y1[k] + hs) * W_ + s_x1[k] + ws;
        float mx = -CUDART_INF_F, my = -CUDART_INF_F;
        for (int y = hs; y < he; ++y) {
            #pragma unroll 2
            for (int xx = 0; xx < nx; ++xx) {
                const float2 v = plane2[idx + xx];
                mx = fmaxf(mx, v.x);
                my = fmaxf(my, v.y);
            }
            idx += W_;
        }

        const size_t ob = ((size_t)s_idx[k] * C_ + c0) * 49 + bin;
        out[ob]      = valid ? mx : 0.0f;
        out[ob + 49] = valid ? my : 0.0f;
    }
}

extern "C" void kernel_launch(void* const* d_in, const int* in_sizes, int n_in,
                              void* d_out, int out_size) {
    const float* features = (const float*)d_in[0];
    const int*   rois     = (const int*)d_in[1];
    float*       out      = (float*)d_out;

    // grid = 4 batches * 128 channel-pairs * 2 roi-halves = 1024 blocks
    roi_pool_c2hi<<<B_ * (C_ / 2) * 2, THREADS>>>(features, rois, out);
}

// round 15
// speedup vs baseline: 1.1004x; 1.1004x over previous
#include <cuda_runtime.h>
#include <math_constants.h>

#define B_      4
#define C_      256
#define H_      64
#define W_      64
#define NROI    128
#define CPB     4
#define THREADS 512

// Dynamic smem layout (69 KB):
//   [0, 65536)      float4 plane4[4096]   — [y*64+x] -> 4 channels
//   [65536, +512)   int    s_idx[128]
//   [66048, +512)   int    s_x1[128]
//   [66560, +512)   int    s_y1[128]
//   [67072, +1024)  uchar  s_hb[128][8]
//   [68096, +1024)  uchar  s_wb[128][8]
//   [69120, +16)    int    s_wcnt[4]
#define SMEM_BYTES 69152

__device__ __forceinline__ float4 fmax4(float4 a, float4 b) {
    return make_float4(fmaxf(a.x, b.x), fmaxf(a.y, b.y),
                       fmaxf(a.z, b.z), fmaxf(a.w, b.w));
}

// Block = (b, 4-channel group, roi-parity), 512 threads (16 warps under one
// 69 KB smem allocation -> 48 warps/SM at 3 blocks/SM). Thread-per-bin tasks,
// 4 channels per LDS.128, two independent accumulator chains for ILP.
// Bin bounds: exact integer math, bit-identical to reference f32 bounds
// (rel_err == 0, rounds 4-14). Deterministic ballot compaction (R10).
__global__ __launch_bounds__(THREADS) void roi_pool_c4w(
    const float* __restrict__ feat,
    const int*   __restrict__ rois,
    float*       __restrict__ out)
{
    extern __shared__ __align__(16) char smem[];
    float4*        plane4 = (float4*)smem;
    int*           s_idx  = (int*)(smem + 65536);
    int*           s_x1   = (int*)(smem + 66048);
    int*           s_y1   = (int*)(smem + 66560);
    unsigned char (*s_hb)[8] = (unsigned char(*)[8])(smem + 67072);
    unsigned char (*s_wb)[8] = (unsigned char(*)[8])(smem + 68096);
    int*           s_wcnt = (int*)(smem + 69120);

    const int tid  = threadIdx.x;
    const int lane = tid & 31;
    const int wid  = tid >> 5;
    const int blk  = blockIdx.x;            // ((b*64 + grp) << 1) | half
    const int half = blk & 1;
    const int bcp  = blk >> 1;
    const int b    = bcp >> 6;
    const int c0   = (bcp & 63) << 2;       // channels c0 .. c0+3

    // ---- phase 0: deterministic compaction (order = original roi index) ----
    bool match = false;
    if (tid < NROI)
        match = (__ldg(rois + tid * 5) == b);
    const unsigned mball = __ballot_sync(0xffffffffu, match);
    if (lane == 0 && wid < 4) s_wcnt[wid] = __popc(mball);
    __syncthreads();
    const int cnt = s_wcnt[0] + s_wcnt[1] + s_wcnt[2] + s_wcnt[3];

    if (match) {
        int p = __popc(mball & ((1u << lane) - 1u));
        for (int w = 0; w < wid; ++w) p += s_wcnt[w];
        const int x1 = __ldg(rois + tid * 5 + 1);
        const int y1 = __ldg(rois + tid * 5 + 2);
        const int x2 = __ldg(rois + tid * 5 + 3);
        const int y2 = __ldg(rois + tid * 5 + 4);
        const int rh = y2 - y1 + 1;          // 5..48
        const int rw = x2 - x1 + 1;          // 5..48
        s_idx[p] = tid;
        s_x1[p]  = x1;
        s_y1[p]  = y1;
        #pragma unroll
        for (int i = 0; i < 8; ++i) {
            s_hb[p][i] = (unsigned char)((i * rh) / 7);
            s_wb[p][i] = (unsigned char)((i * rw) / 7);
        }
    }

    // ---- phase 1: stage 4 planes channel-interleaved (conflict-free) ----
    {
        const float* f0 = feat + ((size_t)b * C_ + c0) * (H_ * W_);
        #pragma unroll
        for (int kk = 0; kk < 8; ++kk) {
            const int g = kk * THREADS + tid;   // 0..4095
            float4 v;
            v.x = __ldg(f0 + g);
            v.y = __ldg(f0 + 4096 + g);
            v.z = __ldg(f0 + 8192 + g);
            v.w = __ldg(f0 + 12288 + g);
            plane4[g] = v;
        }
    }
    __syncthreads();

    // ---- phase 2: thread-per-bin tasks over my roi half, 4 channels each ----
    const int nmine = (cnt > half) ? ((cnt - half + 1) >> 1) : 0;
    const int total = nmine * 49;
    for (int u = tid; u < total; u += THREADS) {
        const int km  = u / 49;
        const int bin = u - km * 49;
        const int k   = half + (km << 1);
        const int i   = (bin * 9363) >> 16;     // bin / 7 for bin < 49
        const int j   = bin - i * 7;

        const int hs = s_hb[k][i], he = s_hb[k][i + 1];
        const int ws = s_wb[k][j], we = s_wb[k][j + 1];
        const int nx = we - ws;
        const bool valid = (he > hs) && (nx > 0);

        int idx = (s_y1[k] + hs) * W_ + s_x1[k] + ws;
        float4 m0 = make_float4(-CUDART_INF_F, -CUDART_INF_F,
                                -CUDART_INF_F, -CUDART_INF_F);
        float4 m1 = m0;
        for (int y = hs; y < he; ++y) {
            int xx = 0;
            for (; xx + 2 <= nx; xx += 2) {     // two independent LDS chains
                m0 = fmax4(m0, plane4[idx + xx]);
                m1 = fmax4(m1, plane4[idx + xx + 1]);
            }
            if (xx < nx)
                m0 = fmax4(m0, plane4[idx + xx]);
            idx += W_;
        }
        m0 = fmax4(m0, m1);

        const size_t ob = ((size_t)s_idx[k] * C_ + c0) * 49 + bin;
        out[ob]           = valid ? m0.x : 0.0f;
        out[ob + 49]      = valid ? m0.y : 0.0f;
        out[ob + 2 * 49]  = valid ? m0.z : 0.0f;
        out[ob + 3 * 49]  = valid ? m0.w : 0.0f;
    }
}

extern "C" void kernel_launch(void* const* d_in, const int* in_sizes, int n_in,
                              void* d_out, int out_size) {
    const float* features = (const float*)d_in[0];
    const int*   rois     = (const int*)d_in[1];
    float*       out      = (float*)d_out;

    cudaFuncSetAttribute(roi_pool_c4w,
                         cudaFuncAttributeMaxDynamicSharedMemorySize, SMEM_BYTES);

    // grid = 4 batches * 64 channel-groups * 2 roi-halves = 512 blocks
    roi_pool_c4w<<<B_ * (C_ / CPB) * 2, THREADS, SMEM_BYTES>>>(features, rois, out);
}

// round 16
// speedup vs baseline: 1.2569x; 1.1423x over previous
#include <cuda_runtime.h>
#include <math_constants.h>

#define B_      4
#define C_      256
#define H_      64
#define W_      64
#define NROI    128
#define CPB     4
#define THREADS 1024

// Dynamic smem layout (69 KB):
//   [0, 65536)      float4 plane4[4096]   — [y*64+x] -> 4 channels
//   [65536, +512)   int    s_idx[128]
//   [66048, +512)   int    s_x1[128]
//   [66560, +512)   int    s_y1[128]
//   [67072, +1024)  uchar  s_hb[128][8]
//   [68096, +1024)  uchar  s_wb[128][8]
//   [69120, +16)    int    s_wcnt[4]
#define SMEM_BYTES 69152

__device__ __forceinline__ float4 fmax4(float4 a, float4 b) {
    return make_float4(fmaxf(a.x, b.x), fmaxf(a.y, b.y),
                       fmaxf(a.z, b.z), fmaxf(a.w, b.w));
}

// Block = (b, 4-channel group), 1024 threads, 2 blocks/SM (64 warps/SM).
// grid = 256 <= single-wave capacity 296: no wave quantization, each plane
// group staged exactly once. Thread-per-bin tasks, 4 channels per LDS.128.
// Bin bounds: exact integer math, bit-identical to reference f32 bounds
// (rel_err == 0, rounds 4-15). Deterministic ballot compaction (R10).
__global__ __launch_bounds__(THREADS, 2) void roi_pool_c4x(
    const float* __restrict__ feat,
    const int*   __restrict__ rois,
    float*       __restrict__ out)
{
    extern __shared__ __align__(16) char smem[];
    float4*        plane4 = (float4*)smem;
    int*           s_idx  = (int*)(smem + 65536);
    int*           s_x1   = (int*)(smem + 66048);
    int*           s_y1   = (int*)(smem + 66560);
    unsigned char (*s_hb)[8] = (unsigned char(*)[8])(smem + 67072);
    unsigned char (*s_wb)[8] = (unsigned char(*)[8])(smem + 68096);
    int*           s_wcnt = (int*)(smem + 69120);

    const int tid  = threadIdx.x;
    const int lane = tid & 31;
    const int wid  = tid >> 5;
    const int blk  = blockIdx.x;            // b*64 + grp
    const int b    = blk >> 6;
    const int c0   = (blk & 63) << 2;       // channels c0 .. c0+3

    // ---- phase 0: deterministic compaction (order = original roi index) ----
    bool match = false;
    if (tid < NROI)
        match = (__ldg(rois + tid * 5) == b);
    const unsigned mball = __ballot_sync(0xffffffffu, match);
    if (lane == 0 && wid < 4) s_wcnt[wid] = __popc(mball);
    __syncthreads();
    const int cnt = s_wcnt[0] + s_wcnt[1] + s_wcnt[2] + s_wcnt[3];

    if (match) {
        int p = __popc(mball & ((1u << lane) - 1u));
        for (int w = 0; w < wid; ++w) p += s_wcnt[w];
        const int x1 = __ldg(rois + tid * 5 + 1);
        const int y1 = __ldg(rois + tid * 5 + 2);
        const int x2 = __ldg(rois + tid * 5 + 3);
        const int y2 = __ldg(rois + tid * 5 + 4);
        const int rh = y2 - y1 + 1;          // 5..48
        const int rw = x2 - x1 + 1;          // 5..48
        s_idx[p] = tid;
        s_x1[p]  = x1;
        s_y1[p]  = y1;
        #pragma unroll
        for (int i = 0; i < 8; ++i) {
            s_hb[p][i] = (unsigned char)((i * rh) / 7);
            s_wb[p][i] = (unsigned char)((i * rw) / 7);
        }
    }

    // ---- phase 1: stage 4 planes channel-interleaved (conflict-free) ----
    {
        const float* f0 = feat + ((size_t)b * C_ + c0) * (H_ * W_);
        #pragma unroll
        for (int kk = 0; kk < 4; ++kk) {
            const int g = kk * THREADS + tid;   // 0..4095
            float4 v;
            v.x = __ldg(f0 + g);
            v.y = __ldg(f0 + 4096 + g);
            v.z = __ldg(f0 + 8192 + g);
            v.w = __ldg(f0 + 12288 + g);
            plane4[g] = v;
        }
    }
    __syncthreads();

    // ---- phase 2: thread-per-bin tasks over all rois, 4 channels each ----
    const int total = cnt * 49;
    for (int u = tid; u < total; u += THREADS) {
        const int k   = u / 49;
        const int bin = u - k * 49;
        const int i   = (bin * 9363) >> 16;     // bin / 7 for bin < 49
        const int j   = bin - i * 7;

        const int hs = s_hb[k][i], he = s_hb[k][i + 1];
        const int ws = s_wb[k][j], we = s_wb[k][j + 1];
        const int nx = we - ws;
        const bool valid = (he > hs) && (nx > 0);

        int idx = (s_y1[k] + hs) * W_ + s_x1[k] + ws;
        float4 m = make_float4(-CUDART_INF_F, -CUDART_INF_F,
                               -CUDART_INF_F, -CUDART_INF_F);
        for (int y = hs; y < he; ++y) {
            #pragma unroll 2
            for (int xx = 0; xx < nx; ++xx)
                m = fmax4(m, plane4[idx + xx]);
            idx += W_;
        }

        const size_t ob = ((size_t)s_idx[k] * C_ + c0) * 49 + bin;
        out[ob]           = valid ? m.x : 0.0f;
        out[ob + 49]      = valid ? m.y : 0.0f;
        out[ob + 2 * 49]  = valid ? m.z : 0.0f;
        out[ob + 3 * 49]  = valid ? m.w : 0.0f;
    }
}

extern "C" void kernel_launch(void* const* d_in, const int* in_sizes, int n_in,
                              void* d_out, int out_size) {
    const float* features = (const float*)d_in[0];
    const int*   rois     = (const int*)d_in[1];
    float*       out      = (float*)d_out;

    cudaFuncSetAttribute(roi_pool_c4x,
                         cudaFuncAttributeMaxDynamicSharedMemorySize, SMEM_BYTES);

    // grid = 4 batches * 64 channel-groups = 256 blocks (single wave)
    roi_pool_c4x<<<B_ * (C_ / CPB), THREADS, SMEM_BYTES>>>(features, rois, out);
}

// round 17
// speedup vs baseline: 1.4726x; 1.1716x over previous
#include <cuda_runtime.h>
#include <math_constants.h>

#define B_      4
#define C_      256
#define H_      64
#define W_      64
#define NROI    128
#define CPB     4
#define THREADS 1024

// Dynamic smem layout (69 KB):
//   [0, 65536)      float4 plane4[4096]   — pixel (y,x) at y*64 + (x ^ (y&7))
//   [65536, +512)   int    s_idx[128]
//   [66048, +512)   int    s_x1[128]
//   [66560, +512)   int    s_y1[128]
//   [67072, +1024)  uchar  s_hb[128][8]
//   [68096, +1024)  uchar  s_wb[128][8]
//   [69120, +16)    int    s_wcnt[4]
#define SMEM_BYTES 69152

__device__ __forceinline__ float4 fmax4(float4 a, float4 b) {
    return make_float4(fmaxf(a.x, b.x), fmaxf(a.y, b.y),
                       fmaxf(a.z, b.z), fmaxf(a.w, b.w));
}

// Block = (b, 4-channel group), 1024 threads, 2 blocks/SM, single wave of 256.
// Thread-per-bin tasks, 4 channels per LDS.128. Plane is XOR-swizzled by row
// (x ^ (y&7)) so the 7 bin-row-groups of a warp hit distinct bank quads.
// Bin bounds: exact integer math, bit-identical to reference f32 bounds
// (rel_err == 0, rounds 4-16). Deterministic ballot compaction (R10).
__global__ __launch_bounds__(THREADS, 2) void roi_pool_c4sw(
    const float* __restrict__ feat,
    const int*   __restrict__ rois,
    float*       __restrict__ out)
{
    extern __shared__ __align__(16) char smem[];
    float4*        plane4 = (float4*)smem;
    int*           s_idx  = (int*)(smem + 65536);
    int*           s_x1   = (int*)(smem + 66048);
    int*           s_y1   = (int*)(smem + 66560);
    unsigned char (*s_hb)[8] = (unsigned char(*)[8])(smem + 67072);
    unsigned char (*s_wb)[8] = (unsigned char(*)[8])(smem + 68096);
    int*           s_wcnt = (int*)(smem + 69120);

    const int tid  = threadIdx.x;
    const int lane = tid & 31;
    const int wid  = tid >> 5;
    const int blk  = blockIdx.x;            // b*64 + grp
    const int b    = blk >> 6;
    const int c0   = (blk & 63) << 2;       // channels c0 .. c0+3

    // ---- phase 0: deterministic compaction (order = original roi index) ----
    bool match = false;
    if (tid < NROI)
        match = (__ldg(rois + tid * 5) == b);
    const unsigned mball = __ballot_sync(0xffffffffu, match);
    if (lane == 0 && wid < 4) s_wcnt[wid] = __popc(mball);
    __syncthreads();
    const int cnt = s_wcnt[0] + s_wcnt[1] + s_wcnt[2] + s_wcnt[3];

    if (match) {
        int p = __popc(mball & ((1u << lane) - 1u));
        for (int w = 0; w < wid; ++w) p += s_wcnt[w];
        const int x1 = __ldg(rois + tid * 5 + 1);
        const int y1 = __ldg(rois + tid * 5 + 2);
        const int x2 = __ldg(rois + tid * 5 + 3);
        const int y2 = __ldg(rois + tid * 5 + 4);
        const int rh = y2 - y1 + 1;          // 5..48
        const int rw = x2 - x1 + 1;          // 5..48
        s_idx[p] = tid;
        s_x1[p]  = x1;
        s_y1[p]  = y1;
        #pragma unroll
        for (int i = 0; i < 8; ++i) {
            s_hb[p][i] = (unsigned char)((i * rh) / 7);
            s_wb[p][i] = (unsigned char)((i * rw) / 7);
        }
    }

    // ---- phase 1: stage 4 planes channel-interleaved, XOR-swizzled by row ----
    {
        const float* f0 = feat + ((size_t)b * C_ + c0) * (H_ * W_);
        #pragma unroll
        for (int kk = 0; kk < 4; ++kk) {
            const int g = kk * THREADS + tid;   // linear pixel 0..4095
            float4 v;
            v.x = __ldg(f0 + g);
            v.y = __ldg(f0 + 4096 + g);
            v.z = __ldg(f0 + 8192 + g);
            v.w = __ldg(f0 + 12288 + g);
            const int y = g >> 6;
            const int x = g & 63;
            plane4[(y << 6) + (x ^ (y & 7))] = v;
        }
    }
    __syncthreads();

    // ---- phase 2: thread-per-bin tasks over all rois, 4 channels each ----
    const int total = cnt * 49;
    for (int u = tid; u < total; u += THREADS) {
        const int k   = u / 49;
        const int bin = u - k * 49;
        const int i   = (bin * 9363) >> 16;     // bin / 7 for bin < 49
        const int j   = bin - i * 7;

        const int hs = s_hb[k][i], he = s_hb[k][i + 1];
        const int ws = s_wb[k][j], we = s_wb[k][j + 1];
        const int nx = we - ws;
        const bool valid = (he > hs) && (nx > 0);

        const int xbase = s_x1[k] + ws;
        float4 m = make_float4(-CUDART_INF_F, -CUDART_INF_F,
                               -CUDART_INF_F, -CUDART_INF_F);
        for (int y = s_y1[k] + hs, ye = s_y1[k] + he; y < ye; ++y) {
            const int sw = y & 7;
            const float4* rowp = plane4 + (y << 6);
            #pragma unroll 2
            for (int xx = 0; xx < nx; ++xx)
                m = fmax4(m, rowp[(xbase + xx) ^ sw]);
        }

        const size_t ob = ((size_t)s_idx[k] * C_ + c0) * 49 + bin;
        out[ob]           = valid ? m.x : 0.0f;
        out[ob + 49]      = valid ? m.y : 0.0f;
        out[ob + 2 * 49]  = valid ? m.z : 0.0f;
        out[ob + 3 * 49]  = valid ? m.w : 0.0f;
    }
}

extern "C" void kernel_launch(void* const* d_in, const int* in_sizes, int n_in,
                              void* d_out, int out_size) {
    const float* features = (const float*)d_in[0];
    const int*   rois     = (const int*)d_in[1];
    float*       out      = (float*)d_out;

    cudaFuncSetAttribute(roi_pool_c4sw,
                         cudaFuncAttributeMaxDynamicSharedMemorySize, SMEM_BYTES);

    // grid = 4 batches * 64 channel-groups = 256 blocks (single wave)
    roi_pool_c4sw<<<B_ * (C_ / CPB), THREADS, SMEM_BYTES>>>(features, rois, out);
}